// round 14
// baseline (speedup 1.0000x reference)
#include <cuda_runtime.h>
#include <cuda_bf16.h>
#include <cstdint>

#define B_    1024
#define D_    256
#define V_    256
#define S_    65536
#define NSPLIT 32
#define NREP  1024

/* output layout (floats) */
#define OFF_RETR   0
#define OFF_SUR    (B_*V_)
#define OFF_KEYS   (OFF_SUR + B_)
#define OFF_VALS   (OFF_KEYS + S_*D_)
#define OFF_AGE    (OFF_VALS + S_*V_)

/* ============ scratch (no allocs allowed) ============ */
__device__ __align__(16) float g_qn[B_*D_];
__device__ float g_q2[B_];
__device__ float g_k2[S_];
__device__ __align__(16) unsigned short g_Kh[(size_t)S_*D_];  /* bf16 hi, [slot][d] */
__device__ __align__(16) unsigned short g_Kl[(size_t)S_*D_];
__device__ __align__(16) unsigned short g_Vth[(size_t)S_*V_]; /* bf16 hi, per-tile [v256][slot64] */
__device__ __align__(16) unsigned short g_Vtl[(size_t)S_*V_];
__device__ __align__(16) float g_Opart[(size_t)B_*NSPLIT*V_]; /* [m1024][sp32][v256] 33.5MB */
__device__ float g_lpart[B_*NSPLIT];
__device__ float g_mpart[B_*NSPLIT];
__device__ float g_surprise[B_];
__device__ float g_smean;
__device__ unsigned int g_hist[4096];
__device__ int g_binT;
__device__ int g_ncand;
__device__ unsigned long long g_candkey[S_];
__device__ int g_candidx[S_];
__device__ int g_sel[NREP];

/* ============ helpers ============ */
__device__ __forceinline__ unsigned int fkey(float f) {
    unsigned int u = __float_as_uint(f);
    return (u & 0x80000000u) ? ~u : (u | 0x80000000u);
}
__device__ __forceinline__ uint32_t smem_u32(const void* p) {
    uint32_t a;
    asm("{ .reg .u64 t; cvta.to.shared.u64 t, %1; cvt.u32.u64 %0, t; }" : "=r"(a) : "l"(p));
    return a;
}
__device__ __forceinline__ void split2(float x0, float x1, uint32_t& h, uint32_t& l) {
    __nv_bfloat16 h0 = __float2bfloat16(x0), h1 = __float2bfloat16(x1);
    float r0 = x0 - __bfloat162float(h0), r1 = x1 - __bfloat162float(h1);
    __nv_bfloat162 hh = __halves2bfloat162(h0, h1);
    __nv_bfloat162 ll = __halves2bfloat162(__float2bfloat16(r0), __float2bfloat16(r1));
    h = *reinterpret_cast<uint32_t*>(&hh);
    l = *reinterpret_cast<uint32_t*>(&ll);
}
__device__ __forceinline__ void ldsm4(uint32_t& r0, uint32_t& r1, uint32_t& r2, uint32_t& r3, uint32_t addr) {
    asm volatile("ldmatrix.sync.aligned.m8n8.x4.shared.b16 {%0,%1,%2,%3}, [%4];"
        : "=r"(r0), "=r"(r1), "=r"(r2), "=r"(r3) : "r"(addr));
}
__device__ __forceinline__ void mma16816(float* c, uint32_t a0, uint32_t a1, uint32_t a2, uint32_t a3,
                                         uint32_t b0, uint32_t b1) {
    asm volatile("mma.sync.aligned.m16n8k16.row.col.f32.bf16.bf16.f32 "
        "{%0,%1,%2,%3}, {%4,%5,%6,%7}, {%8,%9}, {%0,%1,%2,%3};"
        : "+f"(c[0]), "+f"(c[1]), "+f"(c[2]), "+f"(c[3])
        : "r"(a0), "r"(a1), "r"(a2), "r"(a3), "r"(b0), "r"(b1));
}
__device__ __forceinline__ void cp16(uint32_t d, const void* s) {
    asm volatile("cp.async.cg.shared.global [%0], [%1], 16;" :: "r"(d), "l"(s));
}
#define CP_COMMIT() asm volatile("cp.async.commit_group;" ::: "memory")
#define CP_WAIT0()  asm volatile("cp.async.wait_group 0;" ::: "memory")
#define CP_WAIT1()  asm volatile("cp.async.wait_group 1;" ::: "memory")

/* ============ init ============ */
__global__ void init_kernel() {
    int t = blockIdx.x * 256 + threadIdx.x;
    if (t < 4096) g_hist[t] = 0u;
    if (t == 0) g_ncand = 0;
}

/* ============ LayerNorm(query) + q2 ============ */
__global__ void ln_kernel(const float* __restrict__ q, const float* __restrict__ gamma,
                          const float* __restrict__ beta) {
    int b = blockIdx.x, t = threadIdx.x;
    __shared__ float red[8];
    __shared__ float bc;
    float x = q[b*D_ + t];
    float s = x;
    #pragma unroll
    for (int o = 16; o; o >>= 1) s += __shfl_xor_sync(~0u, s, o);
    if ((t & 31) == 0) red[t >> 5] = s;
    __syncthreads();
    if (t == 0) { float v = 0.f; for (int i = 0; i < 8; i++) v += red[i]; bc = v * (1.0f/D_); }
    __syncthreads();
    float mu = bc, d = x - mu;
    __syncthreads();
    s = d * d;
    #pragma unroll
    for (int o = 16; o; o >>= 1) s += __shfl_xor_sync(~0u, s, o);
    if ((t & 31) == 0) red[t >> 5] = s;
    __syncthreads();
    if (t == 0) { float v = 0.f; for (int i = 0; i < 8; i++) v += red[i]; bc = v * (1.0f/D_); }
    __syncthreads();
    float qn = d * rsqrtf(bc + 1e-5f) * gamma[t] + beta[t];
    g_qn[b*D_ + t] = qn;
    __syncthreads();
    s = qn * qn;
    #pragma unroll
    for (int o = 16; o; o >>= 1) s += __shfl_xor_sync(~0u, s, o);
    if ((t & 31) == 0) red[t >> 5] = s;
    __syncthreads();
    if (t == 0) { float v = 0.f; for (int i = 0; i < 8; i++) v += red[i]; g_q2[b] = v; }
}

/* ============ convKV: keys->Kh/Kl + k2, values->Vth/Vtl (transposed) ============ */
__global__ void convKV_kernel(const float* __restrict__ keys, const float* __restrict__ values) {
    extern __shared__ float sv[];      /* 64 x 257 floats */
    int tile = blockIdx.x, slot0 = tile * 64;
    int w = threadIdx.x >> 5, l = threadIdx.x & 31;

    #pragma unroll
    for (int rr = 0; rr < 8; rr++) {
        int row = w*8 + rr;
        const float* src = keys + (size_t)(slot0 + row)*256;
        float ss = 0.f;
        #pragma unroll
        for (int j = 0; j < 4; j++) {
            int wc2 = l + 32*j;
            float x0 = src[2*wc2], x1 = src[2*wc2 + 1];
            ss += x0*x0 + x1*x1;
            uint32_t h, lo; split2(x0, x1, h, lo);
            size_t off = (size_t)(slot0 + row)*256 + 2*wc2;
            *(uint32_t*)(g_Kh + off) = h;
            *(uint32_t*)(g_Kl + off) = lo;
        }
        #pragma unroll
        for (int o = 16; o; o >>= 1) ss += __shfl_xor_sync(~0u, ss, o);
        if (l == 0) g_k2[slot0 + row] = ss;
    }

    for (int idx = threadIdx.x; idx < 64*256; idx += 256) {
        int sl = idx >> 8, v = idx & 255;
        sv[sl*257 + v] = values[(size_t)(slot0 + sl)*256 + v];
    }
    __syncthreads();
    size_t tb = (size_t)tile * 16384;
    for (int idx = threadIdx.x; idx < 256*32; idx += 256) {
        int v = idx >> 5, wc2 = idx & 31;
        uint32_t h, lo; split2(sv[(2*wc2)*257 + v], sv[(2*wc2+1)*257 + v], h, lo);
        size_t off = tb + (size_t)v*64 + 2*wc2;
        *(uint32_t*)(g_Vth + off) = h;
        *(uint32_t*)(g_Vtl + off) = lo;
    }
}

/* ============ fused flash attention: 16 warps, quarter tiles, split-phase pipeline ============ */
/* halves layout */
#define F_QH 0
#define F_QL 16896
#define F_KH 33792
#define F_KL 50688
#define F_VH 67584
#define F_VL 86016
#define F_PH 104448
#define F_PL 109056
#define F_FLT 113664
#define F_SMEM (113664*2 + 704*4)   /* 230144 B */

__global__ void __launch_bounds__(512, 1)
flash_kernel() {
    extern __shared__ unsigned short sh[];
    float* fb  = (float*)(sh + F_FLT);
    float* sPm = fb;            /* [4][64] partial max */
    float* sM  = fb + 256;      /* 64 */
    float* sAl = fb + 320;      /* 64 */
    float* sPl = fb + 384;      /* [4][64] */
    float* sL  = fb + 640;      /* 64 */
    const int tid = threadIdx.x, w = tid >> 5, l = tid & 31;
    const int qb2 = blockIdx.x;  /* 0..15: 64 rows */
    const int sp  = blockIdx.y;  /* 0..31: 2048 slots */
    const int m0 = qb2 * 64;
    const uint32_t smb = smem_u32(sh);
    const int rg = w >> 2, sub = w & 3;
    const int wr = rg * 16;
    const int g = l >> 2, tg = l & 3;
    const int r0 = wr + g, r1 = r0 + 8;

    /* stage Q hi/lo once */
    for (int idx = tid; idx < 64*128; idx += 512) {
        int row = idx >> 7, c = idx & 127;
        const float* src = g_qn + (size_t)(m0 + row)*256 + 2*c;
        uint32_t h, lo; split2(src[0], src[1], h, lo);
        *(uint32_t*)(sh + F_QH + row*264 + 2*c) = h;
        *(uint32_t*)(sh + F_QL + row*264 + 2*c) = lo;
    }
    if (tid < 64) { sM[tid] = -1e30f; sL[tid] = 0.f; }
    const float q20 = g_q2[m0 + r0], q21 = g_q2[m0 + r1];

    /* prologue: stage K(0) then V(0) as separate commit groups */
    {
        int slot0 = sp*32*64;
        const uint4* KHs = (const uint4*)(g_Kh  + (size_t)slot0*256);
        const uint4* KLs = (const uint4*)(g_Kl  + (size_t)slot0*256);
        for (int i = tid; i < 2048; i += 512) {
            int kr = i >> 5, kc = i & 31;
            cp16(smb + (F_KH + kr*264 + kc*8)*2, KHs + i);
            cp16(smb + (F_KL + kr*264 + kc*8)*2, KLs + i);
        }
        CP_COMMIT();
        const uint4* VHs = (const uint4*)(g_Vth + (size_t)(sp*32)*16384);
        const uint4* VLs = (const uint4*)(g_Vtl + (size_t)(sp*32)*16384);
        for (int i = tid; i < 2048; i += 512) {
            int vr = i >> 3, vc = i & 7;
            cp16(smb + (F_VH + vr*72 + vc*8)*2, VHs + i);
            cp16(smb + (F_VL + vr*72 + vc*8)*2, VLs + i);
        }
        CP_COMMIT();
    }

    float acc2[8][4];
    #pragma unroll
    for (int n = 0; n < 8; n++) { acc2[n][0]=0.f; acc2[n][1]=0.f; acc2[n][2]=0.f; acc2[n][3]=0.f; }

    for (int t = 0; t < 32; t++) {
        int tt = sp*32 + t, slot0 = tt*64;

        /* k2 prefetch into regs */
        float2 kk[2];
        {
            const float2* k2p = (const float2*)(g_k2 + slot0 + sub*16);
            kk[0] = k2p[tg];
            kk[1] = k2p[4 + tg];
        }

        CP_WAIT1();          /* K(t) ready */
        __syncthreads();

        /* ---- MMA1: S rows rg*16, slots sub*16 ---- */
        float acc1[2][4];
        #pragma unroll
        for (int n = 0; n < 2; n++) { acc1[n][0]=0.f; acc1[n][1]=0.f; acc1[n][2]=0.f; acc1[n][3]=0.f; }
        #pragma unroll
        for (int ks = 0; ks < 16; ks++) {
            uint32_t ah0,ah1,ah2,ah3, al0,al1,al2,al3;
            int arow = wr + (l & 7) + ((l >> 3) & 1)*8;
            int acol = ks*16 + (l >> 4)*8;
            ldsm4(ah0,ah1,ah2,ah3, smb + (F_QH + arow*264 + acol)*2);
            ldsm4(al0,al1,al2,al3, smb + (F_QL + arow*264 + acol)*2);
            int brow = sub*16 + (l & 7) + (l >> 4)*8;
            int bcol = ks*16 + ((l >> 3) & 1)*8;
            uint32_t bh0,bh1,bh2,bh3, bl0,bl1,bl2,bl3;
            ldsm4(bh0,bh1,bh2,bh3, smb + (F_KH + brow*264 + bcol)*2);
            ldsm4(bl0,bl1,bl2,bl3, smb + (F_KL + brow*264 + bcol)*2);
            mma16816(acc1[0], ah0,ah1,ah2,ah3, bh0,bh1);
            mma16816(acc1[1], ah0,ah1,ah2,ah3, bh2,bh3);
            mma16816(acc1[0], ah0,ah1,ah2,ah3, bl0,bl1);
            mma16816(acc1[1], ah0,ah1,ah2,ah3, bl2,bl3);
            mma16816(acc1[0], al0,al1,al2,al3, bh0,bh1);
            mma16816(acc1[1], al0,al1,al2,al3, bh2,bh3);
        }

        /* ---- logits + warp row max ---- */
        float lg[8];
        float mx0 = -1e30f, mx1 = -1e30f;
        #pragma unroll
        for (int nt = 0; nt < 2; nt++) {
            float k20 = kk[nt].x, k21 = kk[nt].y;
            float v00 = -fmaxf(q20 + k20 - 2.f*acc1[nt][0], 0.f);
            float v01 = -fmaxf(q20 + k21 - 2.f*acc1[nt][1], 0.f);
            float v10 = -fmaxf(q21 + k20 - 2.f*acc1[nt][2], 0.f);
            float v11 = -fmaxf(q21 + k21 - 2.f*acc1[nt][3], 0.f);
            lg[nt*4+0] = v00; lg[nt*4+1] = v01; lg[nt*4+2] = v10; lg[nt*4+3] = v11;
            mx0 = fmaxf(mx0, fmaxf(v00, v01));
            mx1 = fmaxf(mx1, fmaxf(v10, v11));
        }
        mx0 = fmaxf(mx0, __shfl_xor_sync(~0u, mx0, 1));
        mx0 = fmaxf(mx0, __shfl_xor_sync(~0u, mx0, 2));
        mx1 = fmaxf(mx1, __shfl_xor_sync(~0u, mx1, 1));
        mx1 = fmaxf(mx1, __shfl_xor_sync(~0u, mx1, 2));
        if (tg == 0) { sPm[sub*64 + r0] = mx0; sPm[sub*64 + r1] = mx1; }
        __syncthreads();     /* K reads done + sPm visible */

        /* stage K(t+1) — hides behind softmax + MMA2 */
        if (t + 1 < 32) {
            const uint4* KHs = (const uint4*)(g_Kh + (size_t)(slot0 + 64)*256);
            const uint4* KLs = (const uint4*)(g_Kl + (size_t)(slot0 + 64)*256);
            for (int i = tid; i < 2048; i += 512) {
                int kr = i >> 5, kc = i & 31;
                cp16(smb + (F_KH + kr*264 + kc*8)*2, KHs + i);
                cp16(smb + (F_KL + kr*264 + kc*8)*2, KLs + i);
            }
            CP_COMMIT();
        }

        if (tid < 64) {
            float mloc = fmaxf(fmaxf(sPm[tid], sPm[64 + tid]), fmaxf(sPm[128 + tid], sPm[192 + tid]));
            float mold = sM[tid], mnew = fmaxf(mold, mloc);
            sAl[tid] = __expf(mold - mnew);
            sM[tid] = mnew;
        }
        __syncthreads();

        /* ---- P -> smem (hi/lo), l partials, O rescale ---- */
        {
            float mn0 = sM[r0], mn1 = sM[r1];
            float a0 = sAl[r0], a1 = sAl[r1];
            float s0 = 0.f, s1 = 0.f;
            #pragma unroll
            for (int nt = 0; nt < 2; nt++) {
                int n = sub*16 + nt*8 + 2*tg;
                float p00 = __expf(lg[nt*4+0] - mn0), p01 = __expf(lg[nt*4+1] - mn0);
                float p10 = __expf(lg[nt*4+2] - mn1), p11 = __expf(lg[nt*4+3] - mn1);
                s0 += p00 + p01; s1 += p10 + p11;
                uint32_t h, lo;
                split2(p00, p01, h, lo);
                *(uint32_t*)(sh + F_PH + r0*72 + n) = h;
                *(uint32_t*)(sh + F_PL + r0*72 + n) = lo;
                split2(p10, p11, h, lo);
                *(uint32_t*)(sh + F_PH + r1*72 + n) = h;
                *(uint32_t*)(sh + F_PL + r1*72 + n) = lo;
            }
            s0 += __shfl_xor_sync(~0u, s0, 1); s0 += __shfl_xor_sync(~0u, s0, 2);
            s1 += __shfl_xor_sync(~0u, s1, 1); s1 += __shfl_xor_sync(~0u, s1, 2);
            if (tg == 0) { sPl[sub*64 + r0] = s0; sPl[sub*64 + r1] = s1; }
            #pragma unroll
            for (int j = 0; j < 8; j++) {
                acc2[j][0] *= a0; acc2[j][1] *= a0;
                acc2[j][2] *= a1; acc2[j][3] *= a1;
            }
        }
        __syncthreads();     /* P + sPl visible */

        if (tid < 64)
            sL[tid] = sL[tid]*sAl[tid] + sPl[tid] + sPl[64 + tid] + sPl[128 + tid] + sPl[192 + tid];

        if (t + 1 < 32) CP_WAIT1(); else CP_WAIT0();   /* V(t) ready */
        __syncthreads();

        /* ---- MMA2: O += P @ V, rows rg*16, cols sub*64, k=64 ---- */
        #pragma unroll
        for (int ks = 0; ks < 4; ks++) {
            uint32_t ah0,ah1,ah2,ah3, al0,al1,al2,al3;
            int arow = wr + (l & 7) + ((l >> 3) & 1)*8;
            int acol = ks*16 + (l >> 4)*8;
            ldsm4(ah0,ah1,ah2,ah3, smb + (F_PH + arow*72 + acol)*2);
            ldsm4(al0,al1,al2,al3, smb + (F_PL + arow*72 + acol)*2);
            #pragma unroll
            for (int nt2 = 0; nt2 < 4; nt2++) {
                int brow = sub*64 + nt2*16 + (l & 7) + (l >> 4)*8;
                int bcol = ks*16 + ((l >> 3) & 1)*8;
                uint32_t bh0,bh1,bh2,bh3, bl0,bl1,bl2,bl3;
                ldsm4(bh0,bh1,bh2,bh3, smb + (F_VH + brow*72 + bcol)*2);
                ldsm4(bl0,bl1,bl2,bl3, smb + (F_VL + brow*72 + bcol)*2);
                mma16816(acc2[nt2*2],   ah0,ah1,ah2,ah3, bh0,bh1);
                mma16816(acc2[nt2*2+1], ah0,ah1,ah2,ah3, bh2,bh3);
                mma16816(acc2[nt2*2],   ah0,ah1,ah2,ah3, bl0,bl1);
                mma16816(acc2[nt2*2+1], ah0,ah1,ah2,ah3, bl2,bl3);
                mma16816(acc2[nt2*2],   al0,al1,al2,al3, bh0,bh1);
                mma16816(acc2[nt2*2+1], al0,al1,al2,al3, bh2,bh3);
            }
        }
        __syncthreads();     /* V + P consumed */

        /* stage V(t+1) — hides behind next MMA1 */
        if (t + 1 < 32) {
            const uint4* VHs = (const uint4*)(g_Vth + (size_t)(tt + 1)*16384);
            const uint4* VLs = (const uint4*)(g_Vtl + (size_t)(tt + 1)*16384);
            for (int i = tid; i < 2048; i += 512) {
                int vr = i >> 3, vc = i & 7;
                cp16(smb + (F_VH + vr*72 + vc*8)*2, VHs + i);
                cp16(smb + (F_VL + vr*72 + vc*8)*2, VLs + i);
            }
            CP_COMMIT();
        }
    }

    /* ---- epilogue: each warp owns rows rg*16, cols sub*64 ---- */
    #pragma unroll
    for (int j = 0; j < 8; j++) {
        int n = sub*64 + j*8 + 2*tg;
        *(float2*)(g_Opart + ((size_t)(m0 + r0)*NSPLIT + sp)*256 + n) = make_float2(acc2[j][0], acc2[j][1]);
        *(float2*)(g_Opart + ((size_t)(m0 + r1)*NSPLIT + sp)*256 + n) = make_float2(acc2[j][2], acc2[j][3]);
    }
    if (tid < 64) {
        g_mpart[(m0 + tid)*NSPLIT + sp] = sM[tid];
        g_lpart[(m0 + tid)*NSPLIT + sp] = sL[tid];
    }
}

/* ============ combine: logsumexp merge -> retrieved + surprise ============ */
__global__ void combine_kernel(const float* __restrict__ vt, float* __restrict__ out) {
    int b = blockIdx.x, t = threadIdx.x;
    float M = -1e30f;
    #pragma unroll
    for (int i = 0; i < NSPLIT; i++) M = fmaxf(M, g_mpart[b*NSPLIT + i]);
    float wgt[NSPLIT];
    float L = 0.f;
    #pragma unroll
    for (int i = 0; i < NSPLIT; i++) {
        wgt[i] = __expf(g_mpart[b*NSPLIT + i] - M);
        L += g_lpart[b*NSPLIT + i] * wgt[i];
    }
    float acc = 0.f;
    #pragma unroll
    for (int i = 0; i < NSPLIT; i++)
        acc += wgt[i] * g_Opart[((size_t)b*NSPLIT + i)*256 + t];
    float rv = acc / L;
    out[OFF_RETR + (size_t)b*V_ + t] = rv;
    float e = rv - vt[(size_t)b*V_ + t];
    float s = e * e;
    __shared__ float red[8];
    #pragma unroll
    for (int o = 16; o; o >>= 1) s += __shfl_xor_sync(~0u, s, o);
    if ((t & 31) == 0) red[t >> 5] = s;
    __syncthreads();
    if (t == 0) {
        float v = 0.f;
        for (int i = 0; i < 8; i++) v += red[i];
        float sur = v * (1.0f/V_);
        out[OFF_SUR + b] = sur;
        g_surprise[b] = sur;
    }
}

/* ============ mean(surprise) ============ */
__global__ void mean_kernel() {
    int t = threadIdx.x;
    __shared__ float red[8];
    float s = 0.f;
    for (int i = t; i < B_; i += 256) s += g_surprise[i];
    #pragma unroll
    for (int o = 16; o; o >>= 1) s += __shfl_xor_sync(~0u, s, o);
    if ((t & 31) == 0) red[t >> 5] = s;
    __syncthreads();
    if (t == 0) {
        float v = 0.f;
        for (int i = 0; i < 8; i++) v += red[i];
        g_smean = v * (1.0f/B_);
    }
}

/* ============ top-k (value-desc, index-stable) ============ */
__global__ void hist_kernel(const float* __restrict__ age) {
    int i = blockIdx.x * 256 + threadIdx.x;
    atomicAdd(&g_hist[fkey(age[i]) >> 20], 1u);
}
__global__ void thresh_kernel() {
    int cum = 0, T = 0;
    for (int i = 4095; i >= 0; i--) { cum += (int)g_hist[i]; if (cum >= NREP) { T = i; break; } }
    g_binT = T;
}
__global__ void cand_kernel(const float* __restrict__ age) {
    int i = blockIdx.x * 256 + threadIdx.x;
    unsigned int u = fkey(age[i]);
    if ((int)(u >> 20) >= g_binT) {
        int pos = atomicAdd(&g_ncand, 1);
        g_candkey[pos] = ((unsigned long long)u << 32) | (unsigned int)(~(unsigned int)i);
        g_candidx[pos] = i;
    }
}
__global__ void rank_kernel() {
    int n = g_ncand;
    __shared__ int sr[8];
    for (int c = blockIdx.x; c < n; c += gridDim.x) {
        unsigned long long kk = g_candkey[c];
        int cnt = 0;
        for (int j = threadIdx.x; j < n; j += 256) cnt += (g_candkey[j] > kk) ? 1 : 0;
        #pragma unroll
        for (int o = 16; o; o >>= 1) cnt += __shfl_xor_sync(~0u, cnt, o);
        if ((threadIdx.x & 31) == 0) sr[threadIdx.x >> 5] = cnt;
        __syncthreads();
        if (threadIdx.x == 0) {
            int tot = 0;
            for (int i = 0; i < 8; i++) tot += sr[i];
            if (tot < NREP) g_sel[tot] = g_candidx[c];
        }
        __syncthreads();
    }
}

/* ============ bulk copy ============ */
__global__ void copy_kernel(const float* __restrict__ keys, const float* __restrict__ values,
                            const float* __restrict__ age, float* __restrict__ out) {
    size_t gtid = (size_t)blockIdx.x * blockDim.x + threadIdx.x;
    size_t gstr = (size_t)gridDim.x * blockDim.x;
    const float4* K4 = (const float4*)keys;
    const float4* V4 = (const float4*)values;
    float4* oK = (float4*)(out + OFF_KEYS);
    float4* oV = (float4*)(out + OFF_VALS);
    const size_t n4 = (size_t)S_ * D_ / 4;
    for (size_t i = gtid; i < 2 * n4; i += gstr) {
        if (i < n4) oK[i] = K4[i];
        else        oV[i - n4] = V4[i - n4];
    }
    for (size_t i = gtid; i < S_; i += gstr) out[OFF_AGE + i] = age[i] + 1.0f;
}

/* ============ gated EMA scatter ============ */
__global__ void scatter_kernel(const float* __restrict__ keys, const float* __restrict__ values,
                               const float* __restrict__ vt, float* __restrict__ out) {
    int b = blockIdx.x, t = threadIdx.x;
    int slot = g_sel[b];
    float w = 1.0f / (1.0f + __expf(-(g_surprise[b] - g_smean)));
    float decay = 0.99f * (1.0f - w);
    float om = 1.0f - decay;
    out[OFF_KEYS + (size_t)slot*D_ + t] = decay * keys[(size_t)slot*D_ + t] + om * g_qn[(size_t)b*D_ + t];
    out[OFF_VALS + (size_t)slot*V_ + t] = decay * values[(size_t)slot*V_ + t] + om * vt[(size_t)b*V_ + t];
    if (t == 0) out[OFF_AGE + slot] = 1.0f;
}

/* ============ launch ============ */
extern "C" void kernel_launch(void* const* d_in, const int* in_sizes, int n_in,
                              void* d_out, int out_size) {
    const float* query  = (const float*)d_in[0];
    const float* vt     = (const float*)d_in[1];
    const float* keys   = (const float*)d_in[2];
    const float* values = (const float*)d_in[3];
    const float* age    = (const float*)d_in[4];
    const float* gamma  = (const float*)d_in[5];
    const float* beta   = (const float*)d_in[6];
    float* out = (float*)d_out;

    cudaFuncSetAttribute(flash_kernel, cudaFuncAttributeMaxDynamicSharedMemorySize, F_SMEM);
    cudaFuncSetAttribute(convKV_kernel, cudaFuncAttributeMaxDynamicSharedMemorySize, 64*257*4);

    init_kernel<<<16, 256>>>();
    ln_kernel<<<B_, 256>>>(query, gamma, beta);
    convKV_kernel<<<1024, 256, 64*257*4>>>(keys, values);
    flash_kernel<<<dim3(16, 32), 512, F_SMEM>>>();
    combine_kernel<<<B_, 256>>>(vt, out);
    mean_kernel<<<1, 256>>>();
    hist_kernel<<<S_/256, 256>>>(age);
    thresh_kernel<<<1, 1>>>();
    cand_kernel<<<S_/256, 256>>>(age);
    rank_kernel<<<256, 256>>>();
    copy_kernel<<<1024, 256>>>(keys, values, age, out);
    scatter_kernel<<<B_, 256>>>(keys, values, vt, out);
}

// round 17
// speedup vs baseline: 1.0926x; 1.0926x over previous
#include <cuda_runtime.h>
#include <cuda_bf16.h>
#include <cstdint>

#define B_    1024
#define D_    256
#define V_    256
#define S_    65536
#define NSPLIT 32
#define NREP  1024

/* output layout (floats) */
#define OFF_RETR   0
#define OFF_SUR    (B_*V_)
#define OFF_KEYS   (OFF_SUR + B_)
#define OFF_VALS   (OFF_KEYS + S_*D_)
#define OFF_AGE    (OFF_VALS + S_*V_)

/* ============ scratch (no allocs allowed) ============ */
__device__ __align__(16) float g_qn[B_*D_];
__device__ float g_q2[B_];
__device__ float g_k2[S_];
__device__ __align__(16) unsigned short g_Kh[(size_t)S_*D_];  /* bf16 hi, [slot][d] */
__device__ __align__(16) unsigned short g_Kl[(size_t)S_*D_];
__device__ __align__(16) unsigned short g_Vth[(size_t)S_*V_]; /* bf16 hi, per-tile [v256][slot64] */
__device__ __align__(16) unsigned short g_Vtl[(size_t)S_*V_];
__device__ __align__(16) float g_Opart[(size_t)B_*NSPLIT*V_]; /* [m1024][sp32][v256] 33.5MB */
__device__ float g_lpart[B_*NSPLIT];
__device__ float g_mpart[B_*NSPLIT];
__device__ float g_surprise[B_];
__device__ float g_smean;
__device__ unsigned int g_hist[4096];
__device__ int g_binT;
__device__ int g_ncand;
__device__ unsigned long long g_candkey[S_];
__device__ int g_candidx[S_];
__device__ int g_sel[NREP];

/* ============ helpers ============ */
__device__ __forceinline__ unsigned int fkey(float f) {
    unsigned int u = __float_as_uint(f);
    return (u & 0x80000000u) ? ~u : (u | 0x80000000u);
}
__device__ __forceinline__ uint32_t smem_u32(const void* p) {
    uint32_t a;
    asm("{ .reg .u64 t; cvta.to.shared.u64 t, %1; cvt.u32.u64 %0, t; }" : "=r"(a) : "l"(p));
    return a;
}
__device__ __forceinline__ void split2(float x0, float x1, uint32_t& h, uint32_t& l) {
    __nv_bfloat16 h0 = __float2bfloat16(x0), h1 = __float2bfloat16(x1);
    float r0 = x0 - __bfloat162float(h0), r1 = x1 - __bfloat162float(h1);
    __nv_bfloat162 hh = __halves2bfloat162(h0, h1);
    __nv_bfloat162 ll = __halves2bfloat162(__float2bfloat16(r0), __float2bfloat16(r1));
    h = *reinterpret_cast<uint32_t*>(&hh);
    l = *reinterpret_cast<uint32_t*>(&ll);
}
__device__ __forceinline__ void ldsm4(uint32_t& r0, uint32_t& r1, uint32_t& r2, uint32_t& r3, uint32_t addr) {
    asm volatile("ldmatrix.sync.aligned.m8n8.x4.shared.b16 {%0,%1,%2,%3}, [%4];"
        : "=r"(r0), "=r"(r1), "=r"(r2), "=r"(r3) : "r"(addr));
}
__device__ __forceinline__ void mma16816(float* c, uint32_t a0, uint32_t a1, uint32_t a2, uint32_t a3,
                                         uint32_t b0, uint32_t b1) {
    asm volatile("mma.sync.aligned.m16n8k16.row.col.f32.bf16.bf16.f32 "
        "{%0,%1,%2,%3}, {%4,%5,%6,%7}, {%8,%9}, {%0,%1,%2,%3};"
        : "+f"(c[0]), "+f"(c[1]), "+f"(c[2]), "+f"(c[3])
        : "r"(a0), "r"(a1), "r"(a2), "r"(a3), "r"(b0), "r"(b1));
}
__device__ __forceinline__ void cp16(uint32_t d, const void* s) {
    asm volatile("cp.async.cg.shared.global [%0], [%1], 16;" :: "r"(d), "l"(s));
}
#define CP_COMMIT() asm volatile("cp.async.commit_group;" ::: "memory")
#define CP_WAIT0()  asm volatile("cp.async.wait_group 0;" ::: "memory")
#define CP_WAIT1()  asm volatile("cp.async.wait_group 1;" ::: "memory")

/* ============ init ============ */
__global__ void init_kernel() {
    int t = blockIdx.x * 256 + threadIdx.x;
    if (t < 4096) g_hist[t] = 0u;
    if (t == 0) g_ncand = 0;
}

/* ============ LayerNorm(query) + q2 ============ */
__global__ void ln_kernel(const float* __restrict__ q, const float* __restrict__ gamma,
                          const float* __restrict__ beta) {
    int b = blockIdx.x, t = threadIdx.x;
    __shared__ float red[8];
    __shared__ float bc;
    float x = q[b*D_ + t];
    float s = x;
    #pragma unroll
    for (int o = 16; o; o >>= 1) s += __shfl_xor_sync(~0u, s, o);
    if ((t & 31) == 0) red[t >> 5] = s;
    __syncthreads();
    if (t == 0) { float v = 0.f; for (int i = 0; i < 8; i++) v += red[i]; bc = v * (1.0f/D_); }
    __syncthreads();
    float mu = bc, d = x - mu;
    __syncthreads();
    s = d * d;
    #pragma unroll
    for (int o = 16; o; o >>= 1) s += __shfl_xor_sync(~0u, s, o);
    if ((t & 31) == 0) red[t >> 5] = s;
    __syncthreads();
    if (t == 0) { float v = 0.f; for (int i = 0; i < 8; i++) v += red[i]; bc = v * (1.0f/D_); }
    __syncthreads();
    float qn = d * rsqrtf(bc + 1e-5f) * gamma[t] + beta[t];
    g_qn[b*D_ + t] = qn;
    __syncthreads();
    s = qn * qn;
    #pragma unroll
    for (int o = 16; o; o >>= 1) s += __shfl_xor_sync(~0u, s, o);
    if ((t & 31) == 0) red[t >> 5] = s;
    __syncthreads();
    if (t == 0) { float v = 0.f; for (int i = 0; i < 8; i++) v += red[i]; g_q2[b] = v; }
}

/* ============ convKV: keys->Kh/Kl + k2, values->Vth/Vtl (transposed) ============ */
__global__ void convKV_kernel(const float* __restrict__ keys, const float* __restrict__ values) {
    extern __shared__ float sv[];      /* 64 x 257 floats */
    int tile = blockIdx.x, slot0 = tile * 64;
    int w = threadIdx.x >> 5, l = threadIdx.x & 31;

    #pragma unroll
    for (int rr = 0; rr < 8; rr++) {
        int row = w*8 + rr;
        const float* src = keys + (size_t)(slot0 + row)*256;
        float ss = 0.f;
        #pragma unroll
        for (int j = 0; j < 4; j++) {
            int wc2 = l + 32*j;
            float x0 = src[2*wc2], x1 = src[2*wc2 + 1];
            ss += x0*x0 + x1*x1;
            uint32_t h, lo; split2(x0, x1, h, lo);
            size_t off = (size_t)(slot0 + row)*256 + 2*wc2;
            *(uint32_t*)(g_Kh + off) = h;
            *(uint32_t*)(g_Kl + off) = lo;
        }
        #pragma unroll
        for (int o = 16; o; o >>= 1) ss += __shfl_xor_sync(~0u, ss, o);
        if (l == 0) g_k2[slot0 + row] = ss;
    }

    for (int idx = threadIdx.x; idx < 64*256; idx += 256) {
        int sl = idx >> 8, v = idx & 255;
        sv[sl*257 + v] = values[(size_t)(slot0 + sl)*256 + v];
    }
    __syncthreads();
    size_t tb = (size_t)tile * 16384;
    for (int idx = threadIdx.x; idx < 256*32; idx += 256) {
        int v = idx >> 5, wc2 = idx & 31;
        uint32_t h, lo; split2(sv[(2*wc2)*257 + v], sv[(2*wc2+1)*257 + v], h, lo);
        size_t off = tb + (size_t)v*64 + 2*wc2;
        *(uint32_t*)(g_Vth + off) = h;
        *(uint32_t*)(g_Vtl + off) = lo;
    }
}

/* ============ fused flash attention: register-P, PER-WARP online softmax ============ */
#define F_QH 0
#define F_QL 16896
#define F_KH 33792
#define F_KL 50688
#define F_VH 67584
#define F_VL 86016
#define F_FLT 104448
#define F_SMEM (104448*2 + 128*4)   /* 209408 B */

__global__ void __launch_bounds__(256, 1)
flash_kernel() {
    extern __shared__ unsigned short sh[];
    const int tid = threadIdx.x, w = tid >> 5, l = tid & 31;
    const int qb2 = blockIdx.x;  /* 0..15: 64 rows */
    const int sp  = blockIdx.y;  /* 0..31: 2048 slots */
    const int m0 = qb2 * 64;
    const uint32_t smb = smem_u32(sh);
    const int rg = w >> 1, kh = w & 1;
    const int wr = rg * 16;
    const int g = l >> 2, tg = l & 3;
    const int r0 = wr + g, r1 = r0 + 8;

    /* stage Q hi/lo once */
    for (int idx = tid; idx < 64*128; idx += 256) {
        int row = idx >> 7, c = idx & 127;
        const float* src = g_qn + (size_t)(m0 + row)*256 + 2*c;
        uint32_t h, lo; split2(src[0], src[1], h, lo);
        *(uint32_t*)(sh + F_QH + row*264 + 2*c) = h;
        *(uint32_t*)(sh + F_QL + row*264 + 2*c) = lo;
    }
    const float q20 = g_q2[m0 + r0], q21 = g_q2[m0 + r1];
    /* per-warp softmax state (registers) */
    float wm0 = -1e30f, wm1 = -1e30f, wl0 = 0.f, wl1 = 0.f;

    /* prologue: stage K(0) then V(0) as separate commit groups */
    {
        int slot0 = sp*32*64;
        const uint4* KHs = (const uint4*)(g_Kh  + (size_t)slot0*256);
        const uint4* KLs = (const uint4*)(g_Kl  + (size_t)slot0*256);
        for (int i = tid; i < 2048; i += 256) {
            int kr = i >> 5, kc = i & 31;
            cp16(smb + (F_KH + kr*264 + kc*8)*2, KHs + i);
            cp16(smb + (F_KL + kr*264 + kc*8)*2, KLs + i);
        }
        CP_COMMIT();
        const uint4* VHs = (const uint4*)(g_Vth + (size_t)(sp*32)*16384);
        const uint4* VLs = (const uint4*)(g_Vtl + (size_t)(sp*32)*16384);
        for (int i = tid; i < 2048; i += 256) {
            int vr = i >> 3, vc = i & 7;
            cp16(smb + (F_VH + vr*72 + vc*8)*2, VHs + i);
            cp16(smb + (F_VL + vr*72 + vc*8)*2, VLs + i);
        }
        CP_COMMIT();
    }

    float acc2[32][4];
    #pragma unroll
    for (int n = 0; n < 32; n++) { acc2[n][0]=0.f; acc2[n][1]=0.f; acc2[n][2]=0.f; acc2[n][3]=0.f; }

    for (int t = 0; t < 32; t++) {
        int tt = sp*32 + t, slot0 = tt*64;

        /* k2 prefetch into regs */
        float2 kk[4];
        {
            const float2* k2p = (const float2*)(g_k2 + slot0 + kh*32);
            #pragma unroll
            for (int nt = 0; nt < 4; nt++) kk[nt] = k2p[nt*4 + tg];
        }

        CP_WAIT1();          /* K(t) ready (V group pending) */
        __syncthreads();

        /* ---- MMA1: S rows rg*16, slots kh*32+[0,32) ---- */
        float acc1[4][4];
        #pragma unroll
        for (int n = 0; n < 4; n++) { acc1[n][0]=0.f; acc1[n][1]=0.f; acc1[n][2]=0.f; acc1[n][3]=0.f; }
        #pragma unroll
        for (int ks = 0; ks < 16; ks++) {
            uint32_t ah0,ah1,ah2,ah3, al0,al1,al2,al3;
            int arow = wr + (l & 7) + ((l >> 3) & 1)*8;
            int acol = ks*16 + (l >> 4)*8;
            ldsm4(ah0,ah1,ah2,ah3, smb + (F_QH + arow*264 + acol)*2);
            ldsm4(al0,al1,al2,al3, smb + (F_QL + arow*264 + acol)*2);
            #pragma unroll
            for (int nt2 = 0; nt2 < 2; nt2++) {
                int brow = kh*32 + nt2*16 + (l & 7) + (l >> 4)*8;
                int bcol = ks*16 + ((l >> 3) & 1)*8;
                uint32_t bh0,bh1,bh2,bh3, bl0,bl1,bl2,bl3;
                ldsm4(bh0,bh1,bh2,bh3, smb + (F_KH + brow*264 + bcol)*2);
                ldsm4(bl0,bl1,bl2,bl3, smb + (F_KL + brow*264 + bcol)*2);
                mma16816(acc1[nt2*2],   ah0,ah1,ah2,ah3, bh0,bh1);
                mma16816(acc1[nt2*2+1], ah0,ah1,ah2,ah3, bh2,bh3);
                mma16816(acc1[nt2*2],   ah0,ah1,ah2,ah3, bl0,bl1);
                mma16816(acc1[nt2*2+1], ah0,ah1,ah2,ah3, bl2,bl3);
                mma16816(acc1[nt2*2],   al0,al1,al2,al3, bh0,bh1);
                mma16816(acc1[nt2*2+1], al0,al1,al2,al3, bh2,bh3);
            }
        }
        __syncthreads();     /* all warps' K reads done */

        /* stage K(t+1) — in flight during softmax + MMA2 */
        if (t + 1 < 32) {
            const uint4* KHs = (const uint4*)(g_Kh + (size_t)(slot0 + 64)*256);
            const uint4* KLs = (const uint4*)(g_Kl + (size_t)(slot0 + 64)*256);
            for (int i = tid; i < 2048; i += 256) {
                int kr = i >> 5, kc = i & 31;
                cp16(smb + (F_KH + kr*264 + kc*8)*2, KHs + i);
                cp16(smb + (F_KL + kr*264 + kc*8)*2, KLs + i);
            }
            CP_COMMIT();
        }

        /* ---- per-warp softmax: logits, warp max, exp, pack P frags (all regs) ---- */
        float lg[16];
        float mx0 = -1e30f, mx1 = -1e30f;
        #pragma unroll
        for (int nt = 0; nt < 4; nt++) {
            float k20 = kk[nt].x, k21 = kk[nt].y;
            float v00 = -fmaxf(q20 + k20 - 2.f*acc1[nt][0], 0.f);
            float v01 = -fmaxf(q20 + k21 - 2.f*acc1[nt][1], 0.f);
            float v10 = -fmaxf(q21 + k20 - 2.f*acc1[nt][2], 0.f);
            float v11 = -fmaxf(q21 + k21 - 2.f*acc1[nt][3], 0.f);
            lg[nt*4+0] = v00; lg[nt*4+1] = v01; lg[nt*4+2] = v10; lg[nt*4+3] = v11;
            mx0 = fmaxf(mx0, fmaxf(v00, v01));
            mx1 = fmaxf(mx1, fmaxf(v10, v11));
        }
        mx0 = fmaxf(mx0, __shfl_xor_sync(~0u, mx0, 1));
        mx0 = fmaxf(mx0, __shfl_xor_sync(~0u, mx0, 2));
        mx1 = fmaxf(mx1, __shfl_xor_sync(~0u, mx1, 1));
        mx1 = fmaxf(mx1, __shfl_xor_sync(~0u, mx1, 2));
        float mn0 = fmaxf(wm0, mx0), mn1 = fmaxf(wm1, mx1);
        float a0 = __expf(wm0 - mn0), a1 = __expf(wm1 - mn1);
        wm0 = mn0; wm1 = mn1;

        uint32_t ph[2][4], pl[2][4];
        {
            float s0 = 0.f, s1 = 0.f;
            #pragma unroll
            for (int ks = 0; ks < 2; ks++) {
                #pragma unroll
                for (int half = 0; half < 2; half++) {
                    int nt = ks*2 + half;
                    float p00 = __expf(lg[nt*4+0] - mn0), p01 = __expf(lg[nt*4+1] - mn0);
                    float p10 = __expf(lg[nt*4+2] - mn1), p11 = __expf(lg[nt*4+3] - mn1);
                    s0 += p00 + p01; s1 += p10 + p11;
                    uint32_t h0, l0r, h1, l1r;
                    split2(p00, p01, h0, l0r);
                    split2(p10, p11, h1, l1r);
                    ph[ks][half*2]   = h0;  ph[ks][half*2+1] = h1;
                    pl[ks][half*2]   = l0r; pl[ks][half*2+1] = l1r;
                }
            }
            s0 += __shfl_xor_sync(~0u, s0, 1); s0 += __shfl_xor_sync(~0u, s0, 2);
            s1 += __shfl_xor_sync(~0u, s1, 1); s1 += __shfl_xor_sync(~0u, s1, 2);
            wl0 = wl0*a0 + s0;
            wl1 = wl1*a1 + s1;
            #pragma unroll
            for (int j = 0; j < 32; j++) {
                acc2[j][0] *= a0; acc2[j][1] *= a0;
                acc2[j][2] *= a1; acc2[j][3] *= a1;
            }
        }

        if (t + 1 < 32) CP_WAIT1(); else CP_WAIT0();   /* V(t) ready */
        __syncthreads();

        /* ---- MMA2: O += P(regs) @ V, n=256, k = kh*32+[0,32) ---- */
        #pragma unroll
        for (int ks = 0; ks < 2; ks++) {
            #pragma unroll
            for (int nt2 = 0; nt2 < 16; nt2++) {
                int brow = nt2*16 + (l & 7) + (l >> 4)*8;
                int bcol = kh*32 + ks*16 + ((l >> 3) & 1)*8;
                uint32_t bh0,bh1,bh2,bh3, bl0,bl1,bl2,bl3;
                ldsm4(bh0,bh1,bh2,bh3, smb + (F_VH + brow*72 + bcol)*2);
                ldsm4(bl0,bl1,bl2,bl3, smb + (F_VL + brow*72 + bcol)*2);
                mma16816(acc2[nt2*2],   ph[ks][0],ph[ks][1],ph[ks][2],ph[ks][3], bh0,bh1);
                mma16816(acc2[nt2*2+1], ph[ks][0],ph[ks][1],ph[ks][2],ph[ks][3], bh2,bh3);
                mma16816(acc2[nt2*2],   ph[ks][0],ph[ks][1],ph[ks][2],ph[ks][3], bl0,bl1);
                mma16816(acc2[nt2*2+1], ph[ks][0],ph[ks][1],ph[ks][2],ph[ks][3], bl2,bl3);
                mma16816(acc2[nt2*2],   pl[ks][0],pl[ks][1],pl[ks][2],pl[ks][3], bh0,bh1);
                mma16816(acc2[nt2*2+1], pl[ks][0],pl[ks][1],pl[ks][2],pl[ks][3], bh2,bh3);
            }
        }
        __syncthreads();     /* V consumed */

        /* stage V(t+1) — hides behind next MMA1 */
        if (t + 1 < 32) {
            const uint4* VHs = (const uint4*)(g_Vth + (size_t)(tt + 1)*16384);
            const uint4* VLs = (const uint4*)(g_Vtl + (size_t)(tt + 1)*16384);
            for (int i = tid; i < 2048; i += 256) {
                int vr = i >> 3, vc = i & 7;
                cp16(smb + (F_VH + vr*72 + vc*8)*2, VHs + i);
                cp16(smb + (F_VL + vr*72 + vc*8)*2, VLs + i);
            }
            CP_COMMIT();
        }
    }

    /* ---- epilogue: merge kh=0/1 partial softmaxes (dead Q region as buffer) ---- */
    float* red = (float*)sh;                 /* 64 x 264 floats (fits Q region exactly) */
    float* sm0 = (float*)(sh + F_FLT);       /* 64 */
    float* sl0 = sm0 + 64;                   /* 64 */
    if (kh == 0) {
        #pragma unroll
        for (int j = 0; j < 32; j++) {
            int n = j*8 + 2*tg;
            *(float2*)(red + (size_t)r0*264 + n) = make_float2(acc2[j][0], acc2[j][1]);
            *(float2*)(red + (size_t)r1*264 + n) = make_float2(acc2[j][2], acc2[j][3]);
        }
        if (tg == 0) { sm0[r0] = wm0; sm0[r1] = wm1; sl0[r0] = wl0; sl0[r1] = wl1; }
    }
    __syncthreads();
    if (kh == 1) {
        float ma0 = sm0[r0], la0 = sl0[r0];
        float ma1 = sm0[r1], la1 = sl0[r1];
        float M0 = fmaxf(ma0, wm0), M1 = fmaxf(ma1, wm1);
        float wa0 = __expf(ma0 - M0), wb0 = __expf(wm0 - M0);
        float wa1 = __expf(ma1 - M1), wb1 = __expf(wm1 - M1);
        #pragma unroll
        for (int j = 0; j < 32; j++) {
            int n = j*8 + 2*tg;
            float2 o0 = *(float2*)(red + (size_t)r0*264 + n);
            float2 o1 = *(float2*)(red + (size_t)r1*264 + n);
            *(float2*)(g_Opart + ((size_t)(m0 + r0)*NSPLIT + sp)*256 + n) =
                make_float2(o0.x*wa0 + acc2[j][0]*wb0, o0.y*wa0 + acc2[j][1]*wb0);
            *(float2*)(g_Opart + ((size_t)(m0 + r1)*NSPLIT + sp)*256 + n) =
                make_float2(o1.x*wa1 + acc2[j][2]*wb1, o1.y*wa1 + acc2[j][3]*wb1);
        }
        if (tg == 0) {
            g_mpart[(m0 + r0)*NSPLIT + sp] = M0;
            g_mpart[(m0 + r1)*NSPLIT + sp] = M1;
            g_lpart[(m0 + r0)*NSPLIT + sp] = la0*wa0 + wl0*wb0;
            g_lpart[(m0 + r1)*NSPLIT + sp] = la1*wa1 + wl1*wb1;
        }
    }
}

/* ============ combine: logsumexp merge -> retrieved + surprise ============ */
__global__ void combine_kernel(const float* __restrict__ vt, float* __restrict__ out) {
    int b = blockIdx.x, t = threadIdx.x;
    float M = -1e30f;
    #pragma unroll
    for (int i = 0; i < NSPLIT; i++) M = fmaxf(M, g_mpart[b*NSPLIT + i]);
    float wgt[NSPLIT];
    float L = 0.f;
    #pragma unroll
    for (int i = 0; i < NSPLIT; i++) {
        wgt[i] = __expf(g_mpart[b*NSPLIT + i] - M);
        L += g_lpart[b*NSPLIT + i] * wgt[i];
    }
    float acc = 0.f;
    #pragma unroll
    for (int i = 0; i < NSPLIT; i++)
        acc += wgt[i] * g_Opart[((size_t)b*NSPLIT + i)*256 + t];
    float rv = acc / L;
    out[OFF_RETR + (size_t)b*V_ + t] = rv;
    float e = rv - vt[(size_t)b*V_ + t];
    float s = e * e;
    __shared__ float red[8];
    #pragma unroll
    for (int o = 16; o; o >>= 1) s += __shfl_xor_sync(~0u, s, o);
    if ((t & 31) == 0) red[t >> 5] = s;
    __syncthreads();
    if (t == 0) {
        float v = 0.f;
        for (int i = 0; i < 8; i++) v += red[i];
        float sur = v * (1.0f/V_);
        out[OFF_SUR + b] = sur;
        g_surprise[b] = sur;
    }
}

/* ============ mean(surprise) ============ */
__global__ void mean_kernel() {
    int t = threadIdx.x;
    __shared__ float red[8];
    float s = 0.f;
    for (int i = t; i < B_; i += 256) s += g_surprise[i];
    #pragma unroll
    for (int o = 16; o; o >>= 1) s += __shfl_xor_sync(~0u, s, o);
    if ((t & 31) == 0) red[t >> 5] = s;
    __syncthreads();
    if (t == 0) {
        float v = 0.f;
        for (int i = 0; i < 8; i++) v += red[i];
        g_smean = v * (1.0f/B_);
    }
}

/* ============ top-k (value-desc, index-stable) ============ */
__global__ void hist_kernel(const float* __restrict__ age) {
    int i = blockIdx.x * 256 + threadIdx.x;
    atomicAdd(&g_hist[fkey(age[i]) >> 20], 1u);
}
__global__ void thresh_kernel() {
    int cum = 0, T = 0;
    for (int i = 4095; i >= 0; i--) { cum += (int)g_hist[i]; if (cum >= NREP) { T = i; break; } }
    g_binT = T;
}
__global__ void cand_kernel(const float* __restrict__ age) {
    int i = blockIdx.x * 256 + threadIdx.x;
    unsigned int u = fkey(age[i]);
    if ((int)(u >> 20) >= g_binT) {
        int pos = atomicAdd(&g_ncand, 1);
        g_candkey[pos] = ((unsigned long long)u << 32) | (unsigned int)(~(unsigned int)i);
        g_candidx[pos] = i;
    }
}
__global__ void rank_kernel() {
    int n = g_ncand;
    __shared__ int sr[8];
    for (int c = blockIdx.x; c < n; c += gridDim.x) {
        unsigned long long kk = g_candkey[c];
        int cnt = 0;
        for (int j = threadIdx.x; j < n; j += 256) cnt += (g_candkey[j] > kk) ? 1 : 0;
        #pragma unroll
        for (int o = 16; o; o >>= 1) cnt += __shfl_xor_sync(~0u, cnt, o);
        if ((threadIdx.x & 31) == 0) sr[threadIdx.x >> 5] = cnt;
        __syncthreads();
        if (threadIdx.x == 0) {
            int tot = 0;
            for (int i = 0; i < 8; i++) tot += sr[i];
            if (tot < NREP) g_sel[tot] = g_candidx[c];
        }
        __syncthreads();
    }
}

/* ============ bulk copy ============ */
__global__ void copy_kernel(const float* __restrict__ keys, const float* __restrict__ values,
                            const float* __restrict__ age, float* __restrict__ out) {
    size_t gtid = (size_t)blockIdx.x * blockDim.x + threadIdx.x;
    size_t gstr = (size_t)gridDim.x * blockDim.x;
    const float4* K4 = (const float4*)keys;
    const float4* V4 = (const float4*)values;
    float4* oK = (float4*)(out + OFF_KEYS);
    float4* oV = (float4*)(out + OFF_VALS);
    const size_t n4 = (size_t)S_ * D_ / 4;
    for (size_t i = gtid; i < 2 * n4; i += gstr) {
        if (i < n4) oK[i] = K4[i];
        else        oV[i - n4] = V4[i - n4];
    }
    for (size_t i = gtid; i < S_; i += gstr) out[OFF_AGE + i] = age[i] + 1.0f;
}

/* ============ gated EMA scatter ============ */
__global__ void scatter_kernel(const float* __restrict__ keys, const float* __restrict__ values,
                               const float* __restrict__ vt, float* __restrict__ out) {
    int b = blockIdx.x, t = threadIdx.x;
    int slot = g_sel[b];
    float w = 1.0f / (1.0f + __expf(-(g_surprise[b] - g_smean)));
    float decay = 0.99f * (1.0f - w);
    float om = 1.0f - decay;
    out[OFF_KEYS + (size_t)slot*D_ + t] = decay * keys[(size_t)slot*D_ + t] + om * g_qn[(size_t)b*D_ + t];
    out[OFF_VALS + (size_t)slot*V_ + t] = decay * values[(size_t)slot*V_ + t] + om * vt[(size_t)b*V_ + t];
    if (t == 0) out[OFF_AGE + slot] = 1.0f;
}

/* ============ launch ============ */
extern "C" void kernel_launch(void* const* d_in, const int* in_sizes, int n_in,
                              void* d_out, int out_size) {
    const float* query  = (const float*)d_in[0];
    const float* vt     = (const float*)d_in[1];
    const float* keys   = (const float*)d_in[2];
    const float* values = (const float*)d_in[3];
    const float* age    = (const float*)d_in[4];
    const float* gamma  = (const float*)d_in[5];
    const float* beta   = (const float*)d_in[6];
    float* out = (float*)d_out;

    cudaFuncSetAttribute(flash_kernel, cudaFuncAttributeMaxDynamicSharedMemorySize, F_SMEM);
    cudaFuncSetAttribute(convKV_kernel, cudaFuncAttributeMaxDynamicSharedMemorySize, 64*257*4);

    init_kernel<<<16, 256>>>();
    ln_kernel<<<B_, 256>>>(query, gamma, beta);
    convKV_kernel<<<1024, 256, 64*257*4>>>(keys, values);
    flash_kernel<<<dim3(16, 32), 256, F_SMEM>>>();
    combine_kernel<<<B_, 256>>>(vt, out);
    mean_kernel<<<1, 256>>>();
    hist_kernel<<<S_/256, 256>>>(age);
    thresh_kernel<<<1, 1>>>();
    cand_kernel<<<S_/256, 256>>>(age);
    rank_kernel<<<256, 256>>>();
    copy_kernel<<<1024, 256>>>(keys, values, age, out);
    scatter_kernel<<<B_, 256>>>(keys, values, vt, out);
}